// round 12
// baseline (speedup 1.0000x reference)
#include <cuda_runtime.h>
#include <cstdint>

// S_LSTM: 4-layer elementwise LSTM over a 1024x1024 broadcast grid, T=16.
// R11 = R10 (element pairing, f32x2 math, l-outer/t-inner) with hb[] moved
//       from 32 registers to shared memory (conflict-free t-major layout).
//       Regs ~96 -> ~64  =>  7 blocks/SM (28 warps, 56 element streams).

#define TT 16
#define HDIM 1024
#define NL 4
#define HH (HDIM * HDIM)

#define FMA2(d, a, b, c) asm("fma.rn.f32x2 %0, %1, %2, %3;" : "=l"(d) : "l"(a), "l"(b), "l"(c))
#define MUL2(d, a, b)    asm("mul.rn.f32x2 %0, %1, %2;"     : "=l"(d) : "l"(a), "l"(b))
#define STCS64(p, v)     asm volatile("st.global.cs.b64 [%0], %1;" :: "l"(p), "l"(v) : "memory")

__device__ __forceinline__ float tanh_fast(float x) {
    float r; asm("tanh.approx.f32 %0, %1;" : "=f"(r) : "f"(x)); return r;
}
__device__ __forceinline__ uint64_t pk2(float lo, float hi) {
    uint64_t r; unsigned a = __float_as_uint(lo), b = __float_as_uint(hi);
    asm("mov.b64 %0, {%1, %2};" : "=l"(r) : "r"(a), "r"(b)); return r;
}
__device__ __forceinline__ float2 up2(uint64_t v) {
    unsigned a, b; asm("mov.b64 {%0, %1}, %2;" : "=r"(a), "=r"(b) : "l"(v));
    return make_float2(__uint_as_float(a), __uint_as_float(b));
}
// paired sigmoid: u = z/2 pair (weights pre-halved); sig = fma(u, q(u*u), 0.5)
__device__ __forceinline__ uint64_t sigm2(uint64_t u, uint64_t K2, uint64_t K1,
                                          uint64_t K0, uint64_t H5) {
    uint64_t s, q, r;
    MUL2(s, u, u);
    FMA2(q, s, K2, K1);
    FMA2(q, s, q, K0);
    FMA2(r, u, q, H5);
    return r;
}
// paired tanh via 2x MUFU
__device__ __forceinline__ uint64_t tanh2(uint64_t z) {
    float2 v = up2(z);
    return pk2(tanh_fast(v.x), tanh_fast(v.y));
}

__global__ void __launch_bounds__(128, 7) s_lstm_kernel(
    const float* __restrict__ x,
    const float* __restrict__ Wxi, const float* __restrict__ Wxf,
    const float* __restrict__ Wxc, const float* __restrict__ Wxo,
    const float* __restrict__ Whi, const float* __restrict__ Whf,
    const float* __restrict__ Whc, const float* __restrict__ Who,
    const float* __restrict__ Whsi, const float* __restrict__ Whsf,
    const float* __restrict__ Whsc, const float* __restrict__ Whso,
    const float* __restrict__ bi, const float* __restrict__ bf,
    const float* __restrict__ bc, const float* __restrict__ bo,
    float* __restrict__ out)
{
    __shared__ float sx[TT];
    // h of layer below, per timestep, per thread. t-major: thread tid's 8-byte
    // slot at hbs[t][tid] -> banks (2*tid, 2*tid+1) mod 32: conflict-free.
    __shared__ uint64_t hbs[TT][128];

    const int tid = threadIdx.x;
    const int pidx = blockIdx.x * 128 + tid;   // pair index
    const int e0 = pidx * 2;                   // first element (r*H + c), c even
    const int r = e0 >> 10;                    // constant within a block
    const int c0 = e0 & (HDIM - 1);

    if (tid < TT) sx[tid] = x[tid * HDIM + r];

    const uint64_t K2_2 = pk2(0.049435f, 0.049435f);
    const uint64_t K1_2 = pk2(-0.162927f, -0.162927f);
    const uint64_t K0_2 = pk2(0.499786f, 0.499786f);
    const uint64_t H5_2 = pk2(0.5f, 0.5f);
    const uint64_t ZERO2 = pk2(0.0f, 0.0f);

#pragma unroll
    for (int t = 0; t < TT; t++) hbs[t][tid] = ZERO2;  // own slot only
    __syncthreads();  // for sx

#pragma unroll 1
    for (int l = 0; l < NL; l++) {
        // ---- per-layer params: adjacent-element pairs via LDG.64 ----
        const float2 vxi = __ldg((const float2*)(Wxi + l * HDIM + c0));
        const float2 vxf = __ldg((const float2*)(Wxf + l * HDIM + c0));
        const float2 vxo = __ldg((const float2*)(Wxo + l * HDIM + c0));
        const float2 vxc = __ldg((const float2*)(Wxc + l * HDIM + c0));
        const float2 vbi = __ldg((const float2*)(bi  + l * HDIM + c0));
        const float2 vbf = __ldg((const float2*)(bf  + l * HDIM + c0));
        const float2 vbo = __ldg((const float2*)(bo  + l * HDIM + c0));
        const float2 vbc = __ldg((const float2*)(bc  + l * HDIM + c0));
        const float2 vhi = __ldg((const float2*)(Whi + l * HH + e0));
        const float2 vhf = __ldg((const float2*)(Whf + l * HH + e0));
        const float2 vho = __ldg((const float2*)(Who + l * HH + e0));
        const float2 vhc = __ldg((const float2*)(Whc + l * HH + e0));

        const uint64_t wxi2 = pk2(0.5f * vxi.x, 0.5f * vxi.y);
        const uint64_t wxf2 = pk2(0.5f * vxf.x, 0.5f * vxf.y);
        const uint64_t wxo2 = pk2(0.5f * vxo.x, 0.5f * vxo.y);
        const uint64_t wxc2 = pk2(vxc.x, vxc.y);
        const uint64_t bi2  = pk2(0.5f * vbi.x, 0.5f * vbi.y);
        const uint64_t bf2  = pk2(0.5f * vbf.x, 0.5f * vbf.y);
        const uint64_t bo2  = pk2(0.5f * vbo.x, 0.5f * vbo.y);
        const uint64_t bc2  = pk2(vbc.x, vbc.y);
        const uint64_t whi2 = pk2(0.5f * vhi.x, 0.5f * vhi.y);
        const uint64_t whf2 = pk2(0.5f * vhf.x, 0.5f * vhf.y);
        const uint64_t who2 = pk2(0.5f * vho.x, 0.5f * vho.y);
        const uint64_t whc2 = pk2(vhc.x, vhc.y);

        uint64_t wsi2 = ZERO2, wsf2 = ZERO2, wso2 = ZERO2, wsc2 = ZERO2;
        if (l > 0) {
            const float2 vsi = __ldg((const float2*)(Whsi + (l - 1) * HH + e0));
            const float2 vsf = __ldg((const float2*)(Whsf + (l - 1) * HH + e0));
            const float2 vso = __ldg((const float2*)(Whso + (l - 1) * HH + e0));
            const float2 vsc = __ldg((const float2*)(Whsc + (l - 1) * HH + e0));
            wsi2 = pk2(0.5f * vsi.x, 0.5f * vsi.y);
            wsf2 = pk2(0.5f * vsf.x, 0.5f * vsf.y);
            wso2 = pk2(0.5f * vso.x, 0.5f * vso.y);
            wsc2 = pk2(vsc.x, vsc.y);
        }

        uint64_t c2 = ZERO2, h2 = ZERO2;
        const float* pcr = out + e0 + l * HH;          // c plane, t=0
#pragma unroll
        for (int t = 0; t < TT; t++) {
            const float xt = sx[t];                    // broadcast LDS
            const uint64_t xt2 = pk2(xt, xt);
            const uint64_t hbt = hbs[t][tid];          // LDS.64 (own slot)

            uint64_t zi2, zf2, zo2, zc2;
            FMA2(zi2, h2, whi2, bi2);
            FMA2(zf2, h2, whf2, bf2);
            FMA2(zo2, h2, who2, bo2);
            FMA2(zc2, h2, whc2, bc2);
            FMA2(zi2, hbt, wsi2, zi2);
            FMA2(zf2, hbt, wsf2, zf2);
            FMA2(zo2, hbt, wso2, zo2);
            FMA2(zc2, hbt, wsc2, zc2);
            FMA2(zi2, xt2, wxi2, zi2);
            FMA2(zf2, xt2, wxf2, zf2);
            FMA2(zo2, xt2, wxo2, zo2);
            FMA2(zc2, xt2, wxc2, zc2);

            const uint64_t ig2 = sigm2(zi2, K2_2, K1_2, K0_2, H5_2);
            const uint64_t fg2 = sigm2(zf2, K2_2, K1_2, K0_2, H5_2);
            const uint64_t og2 = sigm2(zo2, K2_2, K1_2, K0_2, H5_2);
            const uint64_t cc2 = tanh2(zc2);           // 2x MUFU

            uint64_t icc, cn2, hn2;
            MUL2(icc, ig2, cc2);
            FMA2(cn2, fg2, c2, icc);
            const uint64_t th2 = tanh2(cn2);           // 2x MUFU
            MUL2(hn2, og2, th2);

            c2 = cn2;
            h2 = hn2;
            hbs[t][tid] = hn2;  // STS.64 (own slot) -> layer above

            // ys (T, 2, NL, H, H): s=0 -> c, s=1 -> h
            STCS64(pcr + (size_t)t * (2 * NL * HH), cn2);
            STCS64(pcr + (size_t)t * (2 * NL * HH) + NL * HH, hn2);
        }
    }
}

extern "C" void kernel_launch(void* const* d_in, const int* in_sizes, int n_in,
                              void* d_out, int out_size) {
    const float* x    = (const float*)d_in[0];
    const float* Wxi  = (const float*)d_in[1];
    const float* Wxf  = (const float*)d_in[2];
    const float* Wxc  = (const float*)d_in[3];
    const float* Wxo  = (const float*)d_in[4];
    const float* Whi  = (const float*)d_in[5];
    const float* Whf  = (const float*)d_in[6];
    const float* Whc  = (const float*)d_in[7];
    const float* Who  = (const float*)d_in[8];
    const float* Whsi = (const float*)d_in[9];
    const float* Whsf = (const float*)d_in[10];
    const float* Whsc = (const float*)d_in[11];
    const float* Whso = (const float*)d_in[12];
    const float* bi   = (const float*)d_in[13];
    const float* bf   = (const float*)d_in[14];
    const float* bc   = (const float*)d_in[15];
    const float* bo   = (const float*)d_in[16];
    float* out = (float*)d_out;

    dim3 block(128);
    dim3 grid(HH / 256);  // 4096 blocks, 128 threads x 2 elements each
    s_lstm_kernel<<<grid, block>>>(x, Wxi, Wxf, Wxc, Wxo,
                                   Whi, Whf, Whc, Who,
                                   Whsi, Whsf, Whsc, Whso,
                                   bi, bf, bc, bo, out);
}

// round 13
// speedup vs baseline: 1.0225x; 1.0225x over previous
#include <cuda_runtime.h>
#include <cstdint>

// S_LSTM: 4-layer elementwise LSTM over a 1024x1024 broadcast grid, T=16.
// One thread per (r,c). R12 = R9 (best measured kernel: l-outer/t-inner,
// per-layer params t-invariant in registers, f32x2 gate pairing) plus:
//   - entry L2 prefetch of all 28 per-element weight planes (prologue LDGs
//     become L2 hits instead of DRAM misses)
//   - layer-0 specialized (skip terms structurally zero; h0/c0 folded)

#define TT 16
#define HDIM 1024
#define NL 4
#define HH (HDIM * HDIM)

#define FMA2(d, a, b, c) asm("fma.rn.f32x2 %0, %1, %2, %3;" : "=l"(d) : "l"(a), "l"(b), "l"(c))
#define MUL2(d, a, b)    asm("mul.rn.f32x2 %0, %1, %2;"     : "=l"(d) : "l"(a), "l"(b))
#define PF_L2(p)         asm volatile("prefetch.global.L2 [%0];" :: "l"(p))

__device__ __forceinline__ float tanh_fast(float x) {
    float r; asm("tanh.approx.f32 %0, %1;" : "=f"(r) : "f"(x)); return r;
}
__device__ __forceinline__ uint64_t pk2(float lo, float hi) {
    uint64_t r; unsigned a = __float_as_uint(lo), b = __float_as_uint(hi);
    asm("mov.b64 %0, {%1, %2};" : "=l"(r) : "r"(a), "r"(b)); return r;
}
__device__ __forceinline__ float2 up2(uint64_t v) {
    unsigned a, b; asm("mov.b64 {%0, %1}, %2;" : "=r"(a), "=r"(b) : "l"(v));
    return make_float2(__uint_as_float(a), __uint_as_float(b));
}

__global__ void __launch_bounds__(256, 4) s_lstm_kernel(
    const float* __restrict__ x,
    const float* __restrict__ Wxi, const float* __restrict__ Wxf,
    const float* __restrict__ Wxc, const float* __restrict__ Wxo,
    const float* __restrict__ Whi, const float* __restrict__ Whf,
    const float* __restrict__ Whc, const float* __restrict__ Who,
    const float* __restrict__ Whsi, const float* __restrict__ Whsf,
    const float* __restrict__ Whsc, const float* __restrict__ Whso,
    const float* __restrict__ bi, const float* __restrict__ bf,
    const float* __restrict__ bc, const float* __restrict__ bo,
    float* __restrict__ out)
{
    __shared__ float sx[TT];

    const int tid = threadIdx.x;
    const int idx = blockIdx.x * 256 + tid;  // r*H + c
    const int r = idx >> 10;                 // constant within a block
    const int c = idx & (HDIM - 1);

    if (tid < TT) sx[tid] = x[tid * HDIM + r];
    __syncthreads();

    // Warm L2 with every per-element weight line this thread will need.
#pragma unroll
    for (int l = 0; l < NL; l++) {
        PF_L2(Whi + l * HH + idx);
        PF_L2(Whf + l * HH + idx);
        PF_L2(Whc + l * HH + idx);
        PF_L2(Who + l * HH + idx);
    }
#pragma unroll
    for (int l = 0; l < NL - 1; l++) {
        PF_L2(Whsi + l * HH + idx);
        PF_L2(Whsf + l * HH + idx);
        PF_L2(Whsc + l * HH + idx);
        PF_L2(Whso + l * HH + idx);
    }

    // Packed poly constants for the (i,f) sigmoid pair.
    const uint64_t K2_2 = pk2(0.049435f, 0.049435f);
    const uint64_t K1_2 = pk2(-0.162927f, -0.162927f);
    const uint64_t K0_2 = pk2(0.499786f, 0.499786f);
    const uint64_t H5_2 = pk2(0.5f, 0.5f);

    // h of the layer below, per timestep (register array, fully unrolled use)
    float hb[TT];

    // ================= layer 0 (no skip; c0 = h0 = 0, foldable) =============
    {
        const uint64_t Ax = pk2(0.5f * Wxi[c], 0.5f * Wxf[c]);
        const uint64_t Ay = pk2(0.5f * bi[c],  0.5f * bf[c]);
        const uint64_t Bx = pk2(0.5f * Wxo[c], Wxc[c]);
        const uint64_t By = pk2(0.5f * bo[c],  bc[c]);
        const uint64_t whif = pk2(0.5f * Whi[idx], 0.5f * Whf[idx]);
        const uint64_t whoc = pk2(0.5f * Who[idx], Whc[idx]);

        float cl = 0.0f, hl = 0.0f;
        float* pc = out + idx;                 // c plane, layer 0, t=0
        float* ph = pc + NL * HH;              // h plane

#pragma unroll
        for (int t = 0; t < TT; t++) {
            const float xt = sx[t];
            const uint64_t xt2 = pk2(xt, xt);
            const uint64_t h2  = pk2(hl, hl);

            uint64_t zif, zoc;
            FMA2(zif, h2, whif, Ay);
            FMA2(zif, xt2, Ax, zif);
            FMA2(zoc, h2, whoc, By);
            FMA2(zoc, xt2, Bx, zoc);

            uint64_t s2, q2, sig2;
            MUL2(s2, zif, zif);
            FMA2(q2, s2, K2_2, K1_2);
            FMA2(q2, s2, q2, K0_2);
            FMA2(sig2, zif, q2, H5_2);
            const float2 igfg = up2(sig2);

            const float2 zocv = up2(zoc);                         // (zo/2, zc)
            const float og = fmaf(tanh_fast(zocv.x), 0.5f, 0.5f); // MUFU
            const float cc = tanh_fast(zocv.y);                   // MUFU

            const float cn = fmaf(igfg.y, cl, igfg.x * cc);
            const float hn = og * tanh_fast(cn);                  // MUFU
            cl = cn;
            hl = hn;
            hb[t] = hn;

            __stcs(pc, cn);
            __stcs(ph, hn);
            pc += 2 * NL * HH;
            ph += 2 * NL * HH;
        }
    }

    // ================= layers 1..3 ==========================================
#pragma unroll 1
    for (int l = 1; l < NL; l++) {
        const uint64_t Ax = pk2(0.5f * Wxi[l * HDIM + c], 0.5f * Wxf[l * HDIM + c]);
        const uint64_t Ay = pk2(0.5f * bi[l * HDIM + c],  0.5f * bf[l * HDIM + c]);
        const uint64_t Bx = pk2(0.5f * Wxo[l * HDIM + c], Wxc[l * HDIM + c]);
        const uint64_t By = pk2(0.5f * bo[l * HDIM + c],  bc[l * HDIM + c]);
        const uint64_t whif = pk2(0.5f * Whi[l * HH + idx], 0.5f * Whf[l * HH + idx]);
        const uint64_t whoc = pk2(0.5f * Who[l * HH + idx], Whc[l * HH + idx]);
        const uint64_t wsif = pk2(0.5f * Whsi[(l - 1) * HH + idx],
                                  0.5f * Whsf[(l - 1) * HH + idx]);
        const uint64_t wsoc = pk2(0.5f * Whso[(l - 1) * HH + idx],
                                  Whsc[(l - 1) * HH + idx]);

        float cl = 0.0f, hl = 0.0f;
        float* pc = out + idx + l * HH;        // c plane of this layer, t=0
        float* ph = pc + NL * HH;              // h plane

#pragma unroll
        for (int t = 0; t < TT; t++) {
            const float xt = sx[t];
            const uint64_t xt2 = pk2(xt, xt);
            const uint64_t h2  = pk2(hl, hl);
            const uint64_t hb2 = pk2(hb[t], hb[t]);

            uint64_t zif, zoc;
            FMA2(zif, h2, whif, Ay);
            FMA2(zif, hb2, wsif, zif);
            FMA2(zif, xt2, Ax, zif);
            FMA2(zoc, h2, whoc, By);
            FMA2(zoc, hb2, wsoc, zoc);
            FMA2(zoc, xt2, Bx, zoc);

            uint64_t s2, q2, sig2;
            MUL2(s2, zif, zif);
            FMA2(q2, s2, K2_2, K1_2);
            FMA2(q2, s2, q2, K0_2);
            FMA2(sig2, zif, q2, H5_2);
            const float2 igfg = up2(sig2);

            const float2 zocv = up2(zoc);                         // (zo/2, zc)
            const float og = fmaf(tanh_fast(zocv.x), 0.5f, 0.5f); // MUFU
            const float cc = tanh_fast(zocv.y);                   // MUFU

            const float cn = fmaf(igfg.y, cl, igfg.x * cc);
            const float hn = og * tanh_fast(cn);                  // MUFU
            cl = cn;
            hl = hn;
            hb[t] = hn;  // expose to the layer above

            __stcs(pc, cn);
            __stcs(ph, hn);
            pc += 2 * NL * HH;
            ph += 2 * NL * HH;
        }
    }
}

extern "C" void kernel_launch(void* const* d_in, const int* in_sizes, int n_in,
                              void* d_out, int out_size) {
    const float* x    = (const float*)d_in[0];
    const float* Wxi  = (const float*)d_in[1];
    const float* Wxf  = (const float*)d_in[2];
    const float* Wxc  = (const float*)d_in[3];
    const float* Wxo  = (const float*)d_in[4];
    const float* Whi  = (const float*)d_in[5];
    const float* Whf  = (const float*)d_in[6];
    const float* Whc  = (const float*)d_in[7];
    const float* Who  = (const float*)d_in[8];
    const float* Whsi = (const float*)d_in[9];
    const float* Whsf = (const float*)d_in[10];
    const float* Whsc = (const float*)d_in[11];
    const float* Whso = (const float*)d_in[12];
    const float* bi   = (const float*)d_in[13];
    const float* bf   = (const float*)d_in[14];
    const float* bc   = (const float*)d_in[15];
    const float* bo   = (const float*)d_in[16];
    float* out = (float*)d_out;

    dim3 block(256);
    dim3 grid(HH / 256);  // 4096 blocks, one thread per (r,c)
    s_lstm_kernel<<<grid, block>>>(x, Wxi, Wxf, Wxc, Wxo,
                                   Whi, Whf, Whc, Who,
                                   Whsi, Whsf, Whsc, Whso,
                                   bi, bf, bc, bo, out);
}